// round 1
// baseline (speedup 1.0000x reference)
#include <cuda_runtime.h>
#include <math.h>

#define N_  16
#define C_  128
#define S_  16384
#define K_  64
#define TS  128
#define XSTRIDE 132          // C_+4: 16B aligned rows, conflict-free float4 access
#define NTHREADS 128

// Scratch accumulators (allowed: __device__ globals, no runtime alloc)
__device__ float g_vacc[N_ * K_ * C_];   // [n][k][c]
__device__ float g_asum[N_ * K_];        // [n][k]

// ---------------------------------------------------------------------------
__global__ void nv_zero_kernel() {
    int i = blockIdx.x * blockDim.x + threadIdx.x;
    if (i < N_ * K_ * C_) g_vacc[i] = 0.0f;
    if (i < N_ * K_)      g_asum[i] = 0.0f;
}

// ---------------------------------------------------------------------------
// Main fused kernel: per block = one (n, s-tile of 128 positions).
// Phase 1: per-position L2 norm, logits (64), softmax -> soft tile in smem.
// Phase 2: block-local vlad partial [64x128] in registers, atomicAdd to global.
__global__ __launch_bounds__(NTHREADS, 2)
void nv_main_kernel(const float* __restrict__ x,
                    const float* __restrict__ fc_w,
                    const float* __restrict__ fc_b) {
    extern __shared__ float smem[];
    float* x_sh = smem;                       // [TS][XSTRIDE]  (x tile, [s][c])
    float* w_sh = smem + TS * XSTRIDE;        // [K_][C_] fc_w; later soft [TS][K_]
    float* b_sh = w_sh + K_ * C_;             // [K_]

    const int n  = blockIdx.x >> 7;           // /128 tiles
    const int s0 = (blockIdx.x & 127) * TS;
    const int tid = threadIdx.x;

    // Load fc_w + fc_b into shared
    for (int i = tid; i < K_ * C_; i += NTHREADS) w_sh[i] = fc_w[i];
    if (tid < K_) b_sh[tid] = fc_b[tid];

    // Load x tile: global [n][c][s0+sl] (coalesced over sl) -> smem [sl][c]
    const float* xg = x + (size_t)n * C_ * S_ + s0;
    for (int i = tid; i < C_ * TS; i += NTHREADS) {
        int c = i >> 7;            // i / TS
        int sl = i & (TS - 1);     // i % TS
        x_sh[sl * XSTRIDE + c] = xg[(size_t)c * S_ + sl];
    }
    __syncthreads();

    // ---------------- Phase 1: this thread owns position sl = tid ----------
    float* xr = &x_sh[tid * XSTRIDE];

    // L2 norm over channels
    float ss = 0.0f;
    #pragma unroll
    for (int c = 0; c < C_; c += 4) {
        float4 v = *(const float4*)&xr[c];
        ss = fmaf(v.x, v.x, ss); ss = fmaf(v.y, v.y, ss);
        ss = fmaf(v.z, v.z, ss); ss = fmaf(v.w, v.w, ss);
    }
    float scale = 1.0f / fmaxf(sqrtf(ss), 1e-12f);
    #pragma unroll
    for (int c = 0; c < C_; c += 4) {
        float4 v = *(const float4*)&xr[c];
        v.x *= scale; v.y *= scale; v.z *= scale; v.w *= scale;
        *(float4*)&xr[c] = v;
    }

    // Logits: 64 register accumulators, FMA-pipe bound inner loop
    float logit[K_];
    #pragma unroll
    for (int k = 0; k < K_; k++) logit[k] = b_sh[k];

    #pragma unroll 1
    for (int c = 0; c < C_; c += 4) {
        float4 xv = *(const float4*)&xr[c];
        #pragma unroll
        for (int k = 0; k < K_; k++) {
            float4 wv = *(const float4*)&w_sh[k * C_ + c];  // warp-broadcast
            logit[k] = fmaf(xv.x, wv.x, logit[k]);
            logit[k] = fmaf(xv.y, wv.y, logit[k]);
            logit[k] = fmaf(xv.z, wv.z, logit[k]);
            logit[k] = fmaf(xv.w, wv.w, logit[k]);
        }
    }

    // Softmax over K in registers
    float mx = -INFINITY;
    #pragma unroll
    for (int k = 0; k < K_; k++) mx = fmaxf(mx, logit[k]);
    float se = 0.0f;
    #pragma unroll
    for (int k = 0; k < K_; k++) { float e = __expf(logit[k] - mx); logit[k] = e; se += e; }
    float inv = 1.0f / se;

    __syncthreads();   // everyone done reading fc_w; recycle w_sh as soft tile

    // soft tile layout: soft[sl][k], stride K_ (=64, 16B-aligned rows)
    #pragma unroll
    for (int k = 0; k < K_; k += 4) {
        float4 sv = make_float4(logit[k] * inv, logit[k+1] * inv,
                                logit[k+2] * inv, logit[k+3] * inv);
        *(float4*)&w_sh[tid * K_ + k] = sv;
    }
    __syncthreads();

    // ---------------- Phase 2: vlad partial, 8k x 8c register tile ---------
    const int k0 = (tid & 7) * 8;    // 8 k-groups
    const int c0 = (tid >> 3) * 8;   // 16 c-groups

    float acc[8][8];
    #pragma unroll
    for (int i = 0; i < 8; i++)
        #pragma unroll
        for (int j = 0; j < 8; j++) acc[i][j] = 0.0f;

    #pragma unroll 1
    for (int s = 0; s < TS; s++) {
        float4 sa = *(const float4*)&w_sh[s * K_ + k0];
        float4 sb = *(const float4*)&w_sh[s * K_ + k0 + 4];
        float4 xa = *(const float4*)&x_sh[s * XSTRIDE + c0];
        float4 xb = *(const float4*)&x_sh[s * XSTRIDE + c0 + 4];
        float sk[8] = {sa.x, sa.y, sa.z, sa.w, sb.x, sb.y, sb.z, sb.w};
        float xc[8] = {xa.x, xa.y, xa.z, xa.w, xb.x, xb.y, xb.z, xb.w};
        #pragma unroll
        for (int i = 0; i < 8; i++)
            #pragma unroll
            for (int j = 0; j < 8; j++)
                acc[i][j] = fmaf(sk[i], xc[j], acc[i][j]);
    }

    float* vdst = g_vacc + n * K_ * C_;
    #pragma unroll
    for (int i = 0; i < 8; i++)
        #pragma unroll
        for (int j = 0; j < 8; j++)
            atomicAdd(&vdst[(k0 + i) * C_ + (c0 + j)], acc[i][j]);

    // a_sum partial: threads 0..63 each own one k
    if (tid < K_) {
        float asum = 0.0f;
        #pragma unroll 4
        for (int s = 0; s < TS; s++) asum += w_sh[s * K_ + tid];
        atomicAdd(&g_asum[n * K_ + tid], asum);
    }
}

// ---------------------------------------------------------------------------
// Finalize: vlad = acc - a_sum*centroids; intra-norm per (n,k); global norm.
__global__ __launch_bounds__(128)
void nv_finalize_kernel(const float* __restrict__ centroids,
                        float* __restrict__ out) {
    __shared__ float vsh[K_ * C_];
    __shared__ float wsum[4];

    const int n   = blockIdx.x;
    const int tid = threadIdx.x;
    const int k    = tid >> 1;          // 2 threads per k
    const int cb   = (tid & 1) * 64;    // 64 channels each

    const float* acc = g_vacc + n * K_ * C_;
    const float  ak  = g_asum[n * K_ + k];

    // v = acc - a_sum*centroid ; row sum of squares
    float ssk = 0.0f;
    #pragma unroll 8
    for (int c = 0; c < 64; c++) {
        int idx = k * C_ + cb + c;
        float v = acc[idx] - ak * centroids[idx];
        vsh[idx] = v;
        ssk = fmaf(v, v, ssk);
    }
    ssk += __shfl_xor_sync(0xffffffff, ssk, 1);   // combine the two halves of k
    float rinv = 1.0f / fmaxf(sqrtf(ssk), 1e-12f);

    float tot = 0.0f;
    #pragma unroll 8
    for (int c = 0; c < 64; c++) {
        int idx = k * C_ + cb + c;
        float t = vsh[idx] * rinv;
        vsh[idx] = t;
        tot = fmaf(t, t, tot);
    }

    // block-reduce total sum of squares
    #pragma unroll
    for (int off = 16; off > 0; off >>= 1)
        tot += __shfl_xor_sync(0xffffffff, tot, off);
    if ((tid & 31) == 0) wsum[tid >> 5] = tot;
    __syncthreads();
    float total = wsum[0] + wsum[1] + wsum[2] + wsum[3];
    float ginv = 1.0f / fmaxf(sqrtf(total), 1e-12f);

    float* od = out + (size_t)n * K_ * C_;
    for (int i = tid; i < K_ * C_; i += 128)
        od[i] = vsh[i] * ginv;
}

// ---------------------------------------------------------------------------
extern "C" void kernel_launch(void* const* d_in, const int* in_sizes, int n_in,
                              void* d_out, int out_size) {
    const float* x         = (const float*)d_in[0];   // [16,128,16384]
    const float* fc_w      = (const float*)d_in[1];   // [64,128]
    const float* fc_b      = (const float*)d_in[2];   // [64]
    const float* centroids = (const float*)d_in[3];   // [64,128]
    float* out = (float*)d_out;                       // [16, 8192]

    static const size_t MAIN_SMEM = (TS * XSTRIDE + K_ * C_ + K_) * sizeof(float);
    cudaFuncSetAttribute(nv_main_kernel,
                         cudaFuncAttributeMaxDynamicSharedMemorySize,
                         (int)MAIN_SMEM);

    nv_zero_kernel<<<(N_ * K_ * C_ + 255) / 256, 256>>>();
    nv_main_kernel<<<N_ * (S_ / TS), NTHREADS, MAIN_SMEM>>>(x, fc_w, fc_b);
    nv_finalize_kernel<<<N_, 128>>>(centroids, out);
}

// round 2
// speedup vs baseline: 1.0393x; 1.0393x over previous
#include <cuda_runtime.h>
#include <math.h>

#define N_  16
#define C_  128
#define S_  16384
#define K_  64
#define TS  128
#define XSTRIDE 132          // C_+4: 16B aligned rows, conflict-free float4 access
#define NTHREADS 128

// Scratch accumulators (allowed: __device__ globals, no runtime alloc)
__device__ float g_vacc[N_ * K_ * C_];   // [n][k][c]
__device__ float g_asum[N_ * K_];        // [n][k]

// ---- packed f32x2 helpers (Blackwell FFMA2: 2 fp32 FMAs per instruction) ----
typedef unsigned long long u64t;

__device__ __forceinline__ u64t ffma2(u64t a, u64t b, u64t c) {
    u64t d;
    asm("fma.rn.f32x2 %0, %1, %2, %3;" : "=l"(d) : "l"(a), "l"(b), "l"(c));
    return d;
}
__device__ __forceinline__ u64t pack2(float lo, float hi) {
    union { u64t u; float f[2]; } t; t.f[0] = lo; t.f[1] = hi; return t.u;
}
__device__ __forceinline__ void unpack2(u64t v, float& lo, float& hi) {
    union { u64t u; float f[2]; } t; t.u = v; lo = t.f[0]; hi = t.f[1];
}
union F4U2 { float4 f4; u64t u[2]; };

// ---------------------------------------------------------------------------
__global__ void nv_zero_kernel() {
    int i = blockIdx.x * blockDim.x + threadIdx.x;
    if (i < N_ * K_ * C_) g_vacc[i] = 0.0f;
    if (i < N_ * K_)      g_asum[i] = 0.0f;
}

// ---------------------------------------------------------------------------
// Main fused kernel: per block = one (n, s-tile of 128 positions).
// Phase 1: per-position L2 norm, logits (64) via packed f32x2, softmax.
// Phase 2: block-local vlad partial [64x128] in packed registers, atomicAdd.
__global__ __launch_bounds__(NTHREADS, 2)
void nv_main_kernel(const float* __restrict__ x,
                    const float* __restrict__ fc_w,
                    const float* __restrict__ fc_b) {
    extern __shared__ float smem[];
    float* x_sh = smem;                       // [TS][XSTRIDE]  (x tile, [s][c])
    float* w_sh = smem + TS * XSTRIDE;        // [K_][C_] fc_w; later soft [TS][K_]
    float* b_sh = w_sh + K_ * C_;             // [K_]

    const int n  = blockIdx.x >> 7;           // /128 tiles
    const int s0 = (blockIdx.x & 127) * TS;
    const int tid = threadIdx.x;

    // Load fc_w + fc_b into shared
    for (int i = tid; i < K_ * C_; i += NTHREADS) w_sh[i] = fc_w[i];
    if (tid < K_) b_sh[tid] = fc_b[tid];

    // Load x tile: global [n][c][s0+sl] (coalesced over sl) -> smem [sl][c]
    const float* xg = x + (size_t)n * C_ * S_ + s0;
    for (int i = tid; i < C_ * TS; i += NTHREADS) {
        int c = i >> 7;            // i / TS
        int sl = i & (TS - 1);     // i % TS
        x_sh[sl * XSTRIDE + c] = xg[(size_t)c * S_ + sl];
    }
    __syncthreads();

    // ---------------- Phase 1: this thread owns position sl = tid ----------
    float* xr = &x_sh[tid * XSTRIDE];

    // L2 norm over channels
    float ss = 0.0f;
    #pragma unroll
    for (int c = 0; c < C_; c += 4) {
        float4 v = *(const float4*)&xr[c];
        ss = fmaf(v.x, v.x, ss); ss = fmaf(v.y, v.y, ss);
        ss = fmaf(v.z, v.z, ss); ss = fmaf(v.w, v.w, ss);
    }
    float scale = 1.0f / fmaxf(sqrtf(ss), 1e-12f);
    #pragma unroll
    for (int c = 0; c < C_; c += 4) {
        float4 v = *(const float4*)&xr[c];
        v.x *= scale; v.y *= scale; v.z *= scale; v.w *= scale;
        *(float4*)&xr[c] = v;
    }

    // Logits via packed FFMA2: two passes of 32 clusters (bounds registers).
    // acc2[j] accumulates (even-c partial, odd-c partial) for cluster 32*p+j.
    float logit[K_];
    #pragma unroll 1
    for (int p = 0; p < 2; p++) {
        u64t acc2[32];
        const float* wp = &w_sh[(p << 5) * C_];
        #pragma unroll
        for (int j = 0; j < 32; j++) acc2[j] = pack2(b_sh[(p << 5) + j], 0.0f);

        #pragma unroll 1
        for (int c = 0; c < C_; c += 4) {
            F4U2 xv; xv.f4 = *(const float4*)&xr[c];
            #pragma unroll
            for (int j = 0; j < 32; j++) {
                F4U2 wv; wv.f4 = *(const float4*)&wp[j * C_ + c];  // broadcast
                acc2[j] = ffma2(xv.u[0], wv.u[0], acc2[j]);
                acc2[j] = ffma2(xv.u[1], wv.u[1], acc2[j]);
            }
        }
        #pragma unroll
        for (int j = 0; j < 32; j++) {
            float lo, hi; unpack2(acc2[j], lo, hi);
            logit[(p << 5) + j] = lo + hi;
        }
    }

    // Softmax over K in registers
    float mx = -INFINITY;
    #pragma unroll
    for (int k = 0; k < K_; k++) mx = fmaxf(mx, logit[k]);
    float se = 0.0f;
    #pragma unroll
    for (int k = 0; k < K_; k++) { float e = __expf(logit[k] - mx); logit[k] = e; se += e; }
    float inv = 1.0f / se;

    __syncthreads();   // everyone done reading fc_w; recycle w_sh as soft tile

    // soft tile layout: soft[sl][k], stride K_ (=64, 16B-aligned rows)
    #pragma unroll
    for (int k = 0; k < K_; k += 4) {
        float4 sv = make_float4(logit[k] * inv, logit[k+1] * inv,
                                logit[k+2] * inv, logit[k+3] * inv);
        *(float4*)&w_sh[tid * K_ + k] = sv;
    }
    __syncthreads();

    // ---------------- Phase 2: vlad partial, 8k x 8c tile, packed over c ---
    const int k0 = (tid & 7) * 8;    // 8 k-groups
    const int c0 = (tid >> 3) * 8;   // 16 c-groups

    u64t acc2[8][4];
    #pragma unroll
    for (int i = 0; i < 8; i++)
        #pragma unroll
        for (int j = 0; j < 4; j++) acc2[i][j] = 0ull;

    #pragma unroll 1
    for (int s = 0; s < TS; s++) {
        F4U2 sa, sb, xa, xb;
        sa.f4 = *(const float4*)&w_sh[s * K_ + k0];
        sb.f4 = *(const float4*)&w_sh[s * K_ + k0 + 4];
        xa.f4 = *(const float4*)&x_sh[s * XSTRIDE + c0];
        xb.f4 = *(const float4*)&x_sh[s * XSTRIDE + c0 + 4];
        float sk[8];
        unpack2(sa.u[0], sk[0], sk[1]); unpack2(sa.u[1], sk[2], sk[3]);
        unpack2(sb.u[0], sk[4], sk[5]); unpack2(sb.u[1], sk[6], sk[7]);
        u64t xc2[4] = {xa.u[0], xa.u[1], xb.u[0], xb.u[1]};
        #pragma unroll
        for (int i = 0; i < 8; i++) {
            u64t sk2 = pack2(sk[i], sk[i]);
            #pragma unroll
            for (int j = 0; j < 4; j++)
                acc2[i][j] = ffma2(sk2, xc2[j], acc2[i][j]);
        }
    }

    float* vdst = g_vacc + n * K_ * C_;
    #pragma unroll
    for (int i = 0; i < 8; i++)
        #pragma unroll
        for (int j = 0; j < 4; j++) {
            float lo, hi; unpack2(acc2[i][j], lo, hi);
            atomicAdd(&vdst[(k0 + i) * C_ + (c0 + 2*j)],     lo);
            atomicAdd(&vdst[(k0 + i) * C_ + (c0 + 2*j + 1)], hi);
        }

    // a_sum partial: threads 0..63 each own one k
    if (tid < K_) {
        float asum = 0.0f;
        #pragma unroll 4
        for (int s = 0; s < TS; s++) asum += w_sh[s * K_ + tid];
        atomicAdd(&g_asum[n * K_ + tid], asum);
    }
}

// ---------------------------------------------------------------------------
// Finalize: vlad = acc - a_sum*centroids; intra-norm per (n,k); global norm.
__global__ __launch_bounds__(128)
void nv_finalize_kernel(const float* __restrict__ centroids,
                        float* __restrict__ out) {
    __shared__ float vsh[K_ * C_];
    __shared__ float wsum[4];

    const int n   = blockIdx.x;
    const int tid = threadIdx.x;
    const int k    = tid >> 1;          // 2 threads per k
    const int cb   = (tid & 1) * 64;    // 64 channels each

    const float* acc = g_vacc + n * K_ * C_;
    const float  ak  = g_asum[n * K_ + k];

    // v = acc - a_sum*centroid ; row sum of squares
    float ssk = 0.0f;
    #pragma unroll 8
    for (int c = 0; c < 64; c++) {
        int idx = k * C_ + cb + c;
        float v = acc[idx] - ak * centroids[idx];
        vsh[idx] = v;
        ssk = fmaf(v, v, ssk);
    }
    ssk += __shfl_xor_sync(0xffffffff, ssk, 1);   // combine the two halves of k
    float rinv = 1.0f / fmaxf(sqrtf(ssk), 1e-12f);

    float tot = 0.0f;
    #pragma unroll 8
    for (int c = 0; c < 64; c++) {
        int idx = k * C_ + cb + c;
        float t = vsh[idx] * rinv;
        vsh[idx] = t;
        tot = fmaf(t, t, tot);
    }

    // block-reduce total sum of squares
    #pragma unroll
    for (int off = 16; off > 0; off >>= 1)
        tot += __shfl_xor_sync(0xffffffff, tot, off);
    if ((tid & 31) == 0) wsum[tid >> 5] = tot;
    __syncthreads();
    float total = wsum[0] + wsum[1] + wsum[2] + wsum[3];
    float ginv = 1.0f / fmaxf(sqrtf(total), 1e-12f);

    float* od = out + (size_t)n * K_ * C_;
    for (int i = tid; i < K_ * C_; i += 128)
        od[i] = vsh[i] * ginv;
}

// ---------------------------------------------------------------------------
extern "C" void kernel_launch(void* const* d_in, const int* in_sizes, int n_in,
                              void* d_out, int out_size) {
    const float* x         = (const float*)d_in[0];   // [16,128,16384]
    const float* fc_w      = (const float*)d_in[1];   // [64,128]
    const float* fc_b      = (const float*)d_in[2];   // [64]
    const float* centroids = (const float*)d_in[3];   // [64,128]
    float* out = (float*)d_out;                       // [16, 8192]

    static const size_t MAIN_SMEM = (TS * XSTRIDE + K_ * C_ + K_) * sizeof(float);
    cudaFuncSetAttribute(nv_main_kernel,
                         cudaFuncAttributeMaxDynamicSharedMemorySize,
                         (int)MAIN_SMEM);

    nv_zero_kernel<<<(N_ * K_ * C_ + 255) / 256, 256>>>();
    nv_main_kernel<<<N_ * (S_ / TS), NTHREADS, MAIN_SMEM>>>(x, fc_w, fc_b);
    nv_finalize_kernel<<<N_, 128>>>(centroids, out);
}

// round 3
// speedup vs baseline: 1.1163x; 1.0741x over previous
#include <cuda_runtime.h>
#include <math.h>

#define N_  16
#define C_  128
#define S_  16384
#define K_  64
#define TS  128
#define TILES 4
#define SGROUPS (S_ / (TS * TILES))   // 32
#define XSTRIDE 132
#define NTHREADS 256

__device__ float g_vacc[N_ * K_ * C_];   // [n][k][c]
__device__ float g_asum[N_ * K_];        // [n][k]

typedef unsigned long long u64t;
__device__ __forceinline__ u64t ffma2(u64t a, u64t b, u64t c) {
    u64t d;
    asm("fma.rn.f32x2 %0, %1, %2, %3;" : "=l"(d) : "l"(a), "l"(b), "l"(c));
    return d;
}
__device__ __forceinline__ u64t pack2(float lo, float hi) {
    union { u64t u; float f[2]; } t; t.f[0] = lo; t.f[1] = hi; return t.u;
}
__device__ __forceinline__ void unpack2(u64t v, float& lo, float& hi) {
    union { u64t u; float f[2]; } t; t.u = v; lo = t.f[0]; hi = t.f[1];
}
union F4U2 { float4 f4; u64t u[2]; };

// ---------------------------------------------------------------------------
__global__ void nv_zero_kernel() {
    int i = blockIdx.x * blockDim.x + threadIdx.x;
    if (i < N_ * K_ * C_) g_vacc[i] = 0.0f;
    if (i < N_ * K_)      g_asum[i] = 0.0f;
}

// ---------------------------------------------------------------------------
// Block = (n, s-group of 4 tiles x 128 positions). 256 threads.
// Phase 1 per tile: thread (sl, p) computes 32 logits (K-half p) from RAW x,
//   rescales by L2 norm factor, softmax via scalar max/sum exchange in smem.
// Phase 2 per tile: 256 threads x (8k x 4c) packed-register accumulation,
//   persistent across the 4 tiles; one atomicAdd volley at the end.
__global__ __launch_bounds__(NTHREADS, 2)
void nv_main_kernel(const float* __restrict__ x,
                    const float* __restrict__ fc_w,
                    const float* __restrict__ fc_b) {
    extern __shared__ float smem[];
    float* x_sh   = smem;                          // [TS][XSTRIDE]
    float* w_sh   = x_sh + TS * XSTRIDE;           // [K_][C_] fc_w; recycled as soft [TS][K_]
    float* b_sh   = w_sh + K_ * C_;                // [K_]
    float* max_sh = b_sh + K_;                     // [TS][2]
    float* sum_sh = max_sh + TS * 2;               // [TS][2]

    const int n   = blockIdx.x >> 5;               // / SGROUPS
    const int g   = blockIdx.x & (SGROUPS - 1);
    const int tid = threadIdx.x;
    const int sl  = tid & (TS - 1);                // position within tile
    const int p   = tid >> 7;                      // K-half (0/1)

    // phase-2 ownership: 32 output floats per thread
    const int k0 = (tid & 7) * 8;                  // 8 clusters
    const int c0 = (tid >> 3) * 4;                 // 4 channels

    if (tid < K_) b_sh[tid] = fc_b[tid];

    u64t acc2[4][4];                               // [kpair][c] persistent
    #pragma unroll
    for (int i = 0; i < 4; i++)
        #pragma unroll
        for (int j = 0; j < 4; j++) acc2[i][j] = 0ull;
    float asum_reg = 0.0f;                         // tid<K_ only

    #pragma unroll 1
    for (int t = 0; t < TILES; t++) {
        const int s0 = g * (TS * TILES) + t * TS;
        __syncthreads();   // previous tile's soft/x reads complete

        // load fc_w (w_sh was recycled as soft last tile)
        for (int i = tid; i < K_ * C_; i += NTHREADS) w_sh[i] = fc_w[i];
        // load x tile: [n][c][s0+sl] -> smem [sl][c]
        const float* xg = x + (size_t)n * C_ * S_ + s0;
        for (int i = tid; i < C_ * TS; i += NTHREADS) {
            int c  = i >> 7;
            int s  = i & (TS - 1);
            x_sh[s * XSTRIDE + c] = xg[(size_t)c * S_ + s];
        }
        __syncthreads();

        // ---- Phase 1: raw norm factor + 32 logits for K-half p ----
        const float* xr = &x_sh[sl * XSTRIDE];
        float ss = 0.0f;
        #pragma unroll
        for (int c = 0; c < C_; c += 4) {
            F4U2 v; v.f4 = *(const float4*)&xr[c];
            ss = fmaf(v.f4.x, v.f4.x, ss); ss = fmaf(v.f4.y, v.f4.y, ss);
            ss = fmaf(v.f4.z, v.f4.z, ss); ss = fmaf(v.f4.w, v.f4.w, ss);
        }
        float scale = 1.0f / fmaxf(sqrtf(ss), 1e-12f);

        float logit[32];
        {
            const float* wp = &w_sh[(p << 5) * C_];
            // two sub-passes of 16 clusters to bound registers
            #pragma unroll 1
            for (int sp = 0; sp < 2; sp++) {
                u64t la[16];
                #pragma unroll
                for (int j = 0; j < 16; j++) la[j] = 0ull;
                const float* wq = wp + (sp << 4) * C_;
                #pragma unroll 1
                for (int c = 0; c < C_; c += 4) {
                    F4U2 xv; xv.f4 = *(const float4*)&xr[c];
                    #pragma unroll
                    for (int j = 0; j < 16; j++) {
                        F4U2 wv; wv.f4 = *(const float4*)&wq[j * C_ + c];
                        la[j] = ffma2(xv.u[0], wv.u[0], la[j]);
                        la[j] = ffma2(xv.u[1], wv.u[1], la[j]);
                    }
                }
                #pragma unroll
                for (int j = 0; j < 16; j++) {
                    float lo, hi; unpack2(la[j], lo, hi);
                    logit[(sp << 4) + j] = fmaf(scale, lo + hi,
                                                b_sh[(p << 5) + (sp << 4) + j]);
                }
            }
        }
        float mymax = -INFINITY;
        #pragma unroll
        for (int j = 0; j < 32; j++) mymax = fmaxf(mymax, logit[j]);
        max_sh[sl * 2 + p] = mymax;
        __syncthreads();   // all raw-x reads + w reads done; max exchanged

        // normalize x row in place (p=0 warps only)
        if (p == 0) {
            #pragma unroll
            for (int c = 0; c < C_; c += 4) {
                float4 v = *(const float4*)&xr[c];
                v.x *= scale; v.y *= scale; v.z *= scale; v.w *= scale;
                *(float4*)&xr[c] = v;
            }
        }
        float m = fmaxf(max_sh[sl * 2], max_sh[sl * 2 + 1]);
        float sume = 0.0f;
        #pragma unroll
        for (int j = 0; j < 32; j++) {
            float e = __expf(logit[j] - m);
            logit[j] = e; sume += e;
        }
        sum_sh[sl * 2 + p] = sume;
        __syncthreads();   // sums exchanged; x row normalized

        float inv = 1.0f / (sum_sh[sl * 2] + sum_sh[sl * 2 + 1]);
        #pragma unroll
        for (int j = 0; j < 32; j += 4) {
            float4 sv = make_float4(logit[j] * inv, logit[j+1] * inv,
                                    logit[j+2] * inv, logit[j+3] * inv);
            *(float4*)&w_sh[sl * K_ + (p << 5) + j] = sv;   // soft tile
        }
        __syncthreads();   // soft complete

        // ---- Phase 2: accumulate 8k x 4c, packed over k-pairs ----
        #pragma unroll 1
        for (int s = 0; s < TS; s++) {
            F4U2 sa, sb;
            sa.f4 = *(const float4*)&w_sh[s * K_ + k0];       // k0..k0+3
            sb.f4 = *(const float4*)&w_sh[s * K_ + k0 + 4];   // k0+4..k0+7
            float4 xv = *(const float4*)&x_sh[s * XSTRIDE + c0];
            u64t xd[4] = { pack2(xv.x, xv.x), pack2(xv.y, xv.y),
                           pack2(xv.z, xv.z), pack2(xv.w, xv.w) };
            u64t sk[4] = { sa.u[0], sa.u[1], sb.u[0], sb.u[1] };
            #pragma unroll
            for (int i = 0; i < 4; i++)
                #pragma unroll
                for (int j = 0; j < 4; j++)
                    acc2[i][j] = ffma2(sk[i], xd[j], acc2[i][j]);
        }

        // a_sum partial (threads 0..63, one k each)
        if (tid < K_) {
            float a = 0.0f;
            #pragma unroll 4
            for (int s = 0; s < TS; s++) a += w_sh[s * K_ + tid];
            asum_reg += a;
        }
    }

    // single atomic volley for the whole 4-tile group
    float* vdst = g_vacc + n * K_ * C_;
    #pragma unroll
    for (int i = 0; i < 4; i++)
        #pragma unroll
        for (int j = 0; j < 4; j++) {
            float lo, hi; unpack2(acc2[i][j], lo, hi);
            atomicAdd(&vdst[(k0 + 2*i)     * C_ + c0 + j], lo);
            atomicAdd(&vdst[(k0 + 2*i + 1) * C_ + c0 + j], hi);
        }
    if (tid < K_) atomicAdd(&g_asum[n * K_ + tid], asum_reg);
}

// ---------------------------------------------------------------------------
__global__ __launch_bounds__(128)
void nv_finalize_kernel(const float* __restrict__ centroids,
                        float* __restrict__ out) {
    __shared__ float vsh[K_ * C_];
    __shared__ float wsum[4];

    const int n   = blockIdx.x;
    const int tid = threadIdx.x;
    const int k   = tid >> 1;
    const int cb  = (tid & 1) * 64;

    const float* acc = g_vacc + n * K_ * C_;
    const float  ak  = g_asum[n * K_ + k];

    float ssk = 0.0f;
    #pragma unroll 8
    for (int c = 0; c < 64; c++) {
        int idx = k * C_ + cb + c;
        float v = acc[idx] - ak * centroids[idx];
        vsh[idx] = v;
        ssk = fmaf(v, v, ssk);
    }
    ssk += __shfl_xor_sync(0xffffffff, ssk, 1);
    float rinv = 1.0f / fmaxf(sqrtf(ssk), 1e-12f);

    float tot = 0.0f;
    #pragma unroll 8
    for (int c = 0; c < 64; c++) {
        int idx = k * C_ + cb + c;
        float tv = vsh[idx] * rinv;
        vsh[idx] = tv;
        tot = fmaf(tv, tv, tot);
    }
    #pragma unroll
    for (int off = 16; off > 0; off >>= 1)
        tot += __shfl_xor_sync(0xffffffff, tot, off);
    if ((tid & 31) == 0) wsum[tid >> 5] = tot;
    __syncthreads();
    float total = wsum[0] + wsum[1] + wsum[2] + wsum[3];
    float ginv = 1.0f / fmaxf(sqrtf(total), 1e-12f);

    float* od = out + (size_t)n * K_ * C_;
    for (int i = tid; i < K_ * C_; i += 128)
        od[i] = vsh[i] * ginv;
}

// ---------------------------------------------------------------------------
extern "C" void kernel_launch(void* const* d_in, const int* in_sizes, int n_in,
                              void* d_out, int out_size) {
    const float* x         = (const float*)d_in[0];
    const float* fc_w      = (const float*)d_in[1];
    const float* fc_b      = (const float*)d_in[2];
    const float* centroids = (const float*)d_in[3];
    float* out = (float*)d_out;

    static const size_t MAIN_SMEM =
        (TS * XSTRIDE + K_ * C_ + K_ + TS * 2 + TS * 2) * sizeof(float);
    cudaFuncSetAttribute(nv_main_kernel,
                         cudaFuncAttributeMaxDynamicSharedMemorySize,
                         (int)MAIN_SMEM);

    nv_zero_kernel<<<(N_ * K_ * C_ + 255) / 256, 256>>>();
    nv_main_kernel<<<N_ * SGROUPS, NTHREADS, MAIN_SMEM>>>(x, fc_w, fc_b);
    nv_finalize_kernel<<<N_, 128>>>(centroids, out);
}

// round 4
// speedup vs baseline: 2.0164x; 1.8063x over previous
#include <cuda_runtime.h>
#include <cuda_bf16.h>
#include <math.h>
#include <stdint.h>

#define N_  16
#define C_  128
#define S_  16384
#define K_  64
#define TS  128
#define TILES 4
#define SGROUPS (S_ / (TS * TILES))   // 32
#define NTH 256
#define LDX 136   // bf16 row stride for x tiles [s][c]
#define LDW 136   // bf16 row stride for w [k][c]
#define LDT 136   // bf16 row stride for softT [k][s]
#define LDL 68    // f32 row stride for logits/soft [s][k]

__device__ float g_vacc[N_ * K_ * C_];   // [n][k][c]
__device__ float g_asum[N_ * K_];        // [n][k]

// ---------------------------------------------------------------------------
__device__ __forceinline__ uint32_t s2u(const void* p) {
    uint32_t a;
    asm("{ .reg .u64 t; cvta.to.shared.u64 t, %1; cvt.u32.u64 %0, t; }"
        : "=r"(a) : "l"(p));
    return a;
}
__device__ __forceinline__ void ldsm4(uint32_t* r, uint32_t addr) {
    asm volatile("ldmatrix.sync.aligned.m8n8.x4.shared.b16 {%0,%1,%2,%3}, [%4];"
                 : "=r"(r[0]), "=r"(r[1]), "=r"(r[2]), "=r"(r[3]) : "r"(addr));
}
__device__ __forceinline__ void ldsm2t(uint32_t& r0, uint32_t& r1, uint32_t addr) {
    asm volatile("ldmatrix.sync.aligned.m8n8.x2.trans.shared.b16 {%0,%1}, [%2];"
                 : "=r"(r0), "=r"(r1) : "r"(addr));
}
__device__ __forceinline__ void mma_bf16(float* d, const uint32_t* a,
                                         uint32_t b0, uint32_t b1) {
    asm volatile("mma.sync.aligned.m16n8k16.row.col.f32.bf16.bf16.f32 "
                 "{%0,%1,%2,%3}, {%4,%5,%6,%7}, {%8,%9}, {%0,%1,%2,%3};"
                 : "+f"(d[0]), "+f"(d[1]), "+f"(d[2]), "+f"(d[3])
                 : "r"(a[0]), "r"(a[1]), "r"(a[2]), "r"(a[3]), "r"(b0), "r"(b1));
}

// ---------------------------------------------------------------------------
__global__ void nv_zero_kernel() {
    int i = blockIdx.x * blockDim.x + threadIdx.x;
    if (i < N_ * K_ * C_) g_vacc[i] = 0.0f;
    if (i < N_ * K_)      g_asum[i] = 0.0f;
}

// ---------------------------------------------------------------------------
// smem byte offsets (all 1024-aligned)
#define OFF_XH   0
#define OFF_XL   34816
#define OFF_WH   69632
#define OFF_WL   87040
#define OFF_SH   104448
#define OFF_SL   121856
#define OFF_LOG  139264
#define OFF_BB   174080
#define OFF_PN   174336
#define OFF_PM   175360
#define OFF_PS   176384
#define SMEM_TOT 177408

__global__ __launch_bounds__(NTH, 1)
void nv_main_kernel(const float* __restrict__ x,
                    const float* __restrict__ fc_w,
                    const float* __restrict__ fc_b) {
    extern __shared__ char smem[];
    __nv_bfloat16* XH  = (__nv_bfloat16*)(smem + OFF_XH);
    __nv_bfloat16* XL  = (__nv_bfloat16*)(smem + OFF_XL);
    __nv_bfloat16* WH  = (__nv_bfloat16*)(smem + OFF_WH);
    __nv_bfloat16* WL  = (__nv_bfloat16*)(smem + OFF_WL);
    __nv_bfloat16* SHm = (__nv_bfloat16*)(smem + OFF_SH);
    __nv_bfloat16* SLm = (__nv_bfloat16*)(smem + OFF_SL);
    float* LOG = (float*)(smem + OFF_LOG);
    float* BB  = (float*)(smem + OFF_BB);
    float* PN  = (float*)(smem + OFF_PN);
    float* PM  = (float*)(smem + OFF_PM);
    float* PS  = (float*)(smem + OFF_PS);

    const uint32_t XHu = s2u(XH), XLu = s2u(XL), WHu = s2u(WH), WLu = s2u(WL);
    const uint32_t SHu = s2u(SHm), SLu = s2u(SLm);

    const int n   = blockIdx.x >> 5;
    const int g   = blockIdx.x & (SGROUPS - 1);
    const int tid = threadIdx.x;
    const int l   = tid & 31;
    const int w   = tid >> 5;
    const int sl  = tid & 127;     // position in tile (norm/convert)
    const int hh  = tid >> 7;      // channel half

    // ---- load fc_w hi/lo + bias (once per block) ----
    for (int i = tid; i < K_ * C_; i += NTH) {
        int k = i >> 7, c = i & 127;
        float v = fc_w[i];
        __nv_bfloat16 hi = __float2bfloat16(v);
        WH[k * LDW + c] = hi;
        WL[k * LDW + c] = __float2bfloat16(v - __bfloat162float(hi));
    }
    if (tid < K_) BB[tid] = fc_b[tid];

    // persistent GEMM2 accumulators: warp w owns m16 stripe (w&3), n64 (w>>2)
    const int m0b = (w & 3) * 16;
    const int nb  = (w >> 2) * 64;
    float vacc[8][4];
    #pragma unroll
    for (int j = 0; j < 8; j++)
        #pragma unroll
        for (int q = 0; q < 4; q++) vacc[j][q] = 0.0f;
    float areg = 0.0f;   // a_sum (tid<64)

    #pragma unroll 1
    for (int t = 0; t < TILES; t++) {
        const int s0 = g * (TS * TILES) + t * TS;
        const float* xg = x + (size_t)n * C_ * S_ + s0;
        __syncthreads();                         // S0: prev tile consumers done

        // ---- pass 1: squared-sum halves ----
        float ss = 0.0f;
        #pragma unroll 8
        for (int c = hh * 64; c < hh * 64 + 64; c++) {
            float v = xg[(size_t)c * S_ + sl];
            ss = fmaf(v, v, ss);
        }
        PN[sl * 2 + hh] = ss;
        __syncthreads();                         // S1

        // ---- pass 2: normalize + bf16 hi/lo convert ----
        float scale = 1.0f / fmaxf(sqrtf(PN[sl * 2] + PN[sl * 2 + 1]), 1e-12f);
        #pragma unroll 4
        for (int c = hh * 64; c < hh * 64 + 64; c += 2) {
            float v0 = xg[(size_t)c * S_ + sl] * scale;
            float v1 = xg[(size_t)(c + 1) * S_ + sl] * scale;
            __nv_bfloat16 h0 = __float2bfloat16(v0);
            __nv_bfloat16 h1 = __float2bfloat16(v1);
            __nv_bfloat162 hp; hp.x = h0; hp.y = h1;
            __nv_bfloat162 lp;
            lp.x = __float2bfloat16(v0 - __bfloat162float(h0));
            lp.y = __float2bfloat16(v1 - __bfloat162float(h1));
            *(__nv_bfloat162*)&XH[sl * LDX + c] = hp;
            *(__nv_bfloat162*)&XL[sl * LDX + c] = lp;
        }
        __syncthreads();                         // S2: XH/XL ready

        // ---- GEMM1: logits[TS,K] = xn @ w^T  (3-term bf16 hi/lo) ----
        {
            const int m0 = w * 16;
            float lacc[8][4];
            #pragma unroll
            for (int j = 0; j < 8; j++)
                #pragma unroll
                for (int q = 0; q < 4; q++) lacc[j][q] = 0.0f;

            uint32_t aoffA = (uint32_t)(((m0 + (l & 15)) * LDX + ((l >> 4) << 3)) * 2);
            uint32_t boffB = (uint32_t)(((((l >> 4) << 3) + (l & 7)) * LDW
                                        + (((l >> 3) & 1) << 3)) * 2);
            #pragma unroll 1
            for (int kc = 0; kc < 8; kc++) {
                uint32_t axh[4], axl[4];
                ldsm4(axh, XHu + aoffA + kc * 32);
                ldsm4(axl, XLu + aoffA + kc * 32);
                #pragma unroll
                for (int j = 0; j < 4; j++) {
                    uint32_t bwh[4], bwl[4];
                    uint32_t bo = boffB + kc * 32 + j * 16 * LDW * 2;
                    ldsm4(bwh, WHu + bo);
                    ldsm4(bwl, WLu + bo);
                    mma_bf16(lacc[2*j],   axh, bwh[0], bwh[1]);
                    mma_bf16(lacc[2*j+1], axh, bwh[2], bwh[3]);
                    mma_bf16(lacc[2*j],   axl, bwh[0], bwh[1]);
                    mma_bf16(lacc[2*j+1], axl, bwh[2], bwh[3]);
                    mma_bf16(lacc[2*j],   axh, bwl[0], bwl[1]);
                    mma_bf16(lacc[2*j+1], axh, bwl[2], bwl[3]);
                }
            }
            // store logits to LOG
            int r0 = m0 + (l >> 2);
            int cst = (l & 3) * 2;
            #pragma unroll
            for (int j = 0; j < 8; j++) {
                int cc = j * 8 + cst;
                LOG[r0 * LDL + cc]           = lacc[j][0];
                LOG[r0 * LDL + cc + 1]       = lacc[j][1];
                LOG[(r0 + 8) * LDL + cc]     = lacc[j][2];
                LOG[(r0 + 8) * LDL + cc + 1] = lacc[j][3];
            }
        }
        __syncthreads();                         // S3: logits complete

        // ---- softmax: thread (s = tid>>1, half = tid&1) handles 32 k ----
        {
            const int sp = tid >> 1;
            const int ph = tid & 1;
            const int kb = ph * 32;
            float lv[32];
            float mx = -INFINITY;
            #pragma unroll
            for (int i = 0; i < 32; i++) {
                lv[i] = LOG[sp * LDL + kb + i] + BB[kb + i];
                mx = fmaxf(mx, lv[i]);
            }
            PM[sp * 2 + ph] = mx;
            __syncthreads();                     // S4
            float m = fmaxf(PM[sp * 2], PM[sp * 2 + 1]);
            float se = 0.0f;
            #pragma unroll
            for (int i = 0; i < 32; i++) {
                float e = __expf(lv[i] - m);
                lv[i] = e; se += e;
            }
            PS[sp * 2 + ph] = se;
            __syncthreads();                     // S5
            float inv = 1.0f / (PS[sp * 2] + PS[sp * 2 + 1]);
            #pragma unroll
            for (int i = 0; i < 32; i++) {
                float sv = lv[i] * inv;
                LOG[sp * LDL + kb + i] = sv;               // fp32 soft (a_sum)
                __nv_bfloat16 sh_ = __float2bfloat16(sv);
                SHm[(kb + i) * LDT + sp] = sh_;
                SLm[(kb + i) * LDT + sp] =
                    __float2bfloat16(sv - __bfloat162float(sh_));
            }
        }
        __syncthreads();                         // S6: soft ready

        // ---- GEMM2: vlad[K,C] += softT @ xn (3-term), persistent accum ----
        #pragma unroll 1
        for (int ks = 0; ks < 8; ks++) {
            int sb = ks * 16;
            uint32_t aoff = (uint32_t)(((m0b + (l & 15)) * LDT + sb
                                       + ((l >> 4) << 3)) * 2);
            uint32_t ash[4], asl[4];
            ldsm4(ash, SHu + aoff);
            ldsm4(asl, SLu + aoff);
            uint32_t boff = (uint32_t)(((sb + (l & 15)) * LDX) * 2);
            #pragma unroll
            for (int j = 0; j < 8; j++) {
                int n0 = nb + j * 8;
                uint32_t bxh0, bxh1, bxl0, bxl1;
                ldsm2t(bxh0, bxh1, XHu + boff + n0 * 2);
                ldsm2t(bxl0, bxl1, XLu + boff + n0 * 2);
                mma_bf16(vacc[j], ash, bxh0, bxh1);
                mma_bf16(vacc[j], asl, bxh0, bxh1);
                mma_bf16(vacc[j], ash, bxl0, bxl1);
            }
        }

        // ---- a_sum column sums from fp32 soft ----
        if (tid < K_) {
            float a = 0.0f;
            #pragma unroll 8
            for (int s = 0; s < TS; s++) a += LOG[s * LDL + tid];
            areg += a;
        }
    }

    // ---- atomic volley ----
    float* vdst = g_vacc + n * K_ * C_;
    {
        int r0 = m0b + (l >> 2);
        int cst = (l & 3) * 2;
        #pragma unroll
        for (int j = 0; j < 8; j++) {
            int c = nb + j * 8 + cst;
            atomicAdd(&vdst[r0 * C_ + c],           vacc[j][0]);
            atomicAdd(&vdst[r0 * C_ + c + 1],       vacc[j][1]);
            atomicAdd(&vdst[(r0 + 8) * C_ + c],     vacc[j][2]);
            atomicAdd(&vdst[(r0 + 8) * C_ + c + 1], vacc[j][3]);
        }
    }
    if (tid < K_) atomicAdd(&g_asum[n * K_ + tid], areg);
}

// ---------------------------------------------------------------------------
__global__ __launch_bounds__(128)
void nv_finalize_kernel(const float* __restrict__ centroids,
                        float* __restrict__ out) {
    __shared__ float vsh[K_ * C_];
    __shared__ float wsum[4];

    const int n   = blockIdx.x;
    const int tid = threadIdx.x;
    const int k   = tid >> 1;
    const int cb  = (tid & 1) * 64;

    const float* acc = g_vacc + n * K_ * C_;
    const float  ak  = g_asum[n * K_ + k];

    float ssk = 0.0f;
    #pragma unroll 8
    for (int c = 0; c < 64; c++) {
        int idx = k * C_ + cb + c;
        float v = acc[idx] - ak * centroids[idx];
        vsh[idx] = v;
        ssk = fmaf(v, v, ssk);
    }
    ssk += __shfl_xor_sync(0xffffffff, ssk, 1);
    float rinv = 1.0f / fmaxf(sqrtf(ssk), 1e-12f);

    float tot = 0.0f;
    #pragma unroll 8
    for (int c = 0; c < 64; c++) {
        int idx = k * C_ + cb + c;
        float tv = vsh[idx] * rinv;
        vsh[idx] = tv;
        tot = fmaf(tv, tv, tot);
    }
    #pragma unroll
    for (int off = 16; off > 0; off >>= 1)
        tot += __shfl_xor_sync(0xffffffff, tot, off);
    if ((tid & 31) == 0) wsum[tid >> 5] = tot;
    __syncthreads();
    float total = wsum[0] + wsum[1] + wsum[2] + wsum[3];
    float ginv = 1.0f / fmaxf(sqrtf(total), 1e-12f);

    float* od = out + (size_t)n * K_ * C_;
    for (int i = tid; i < K_ * C_; i += 128)
        od[i] = vsh[i] * ginv;
}

// ---------------------------------------------------------------------------
extern "C" void kernel_launch(void* const* d_in, const int* in_sizes, int n_in,
                              void* d_out, int out_size) {
    const float* x         = (const float*)d_in[0];
    const float* fc_w      = (const float*)d_in[1];
    const float* fc_b      = (const float*)d_in[2];
    const float* centroids = (const float*)d_in[3];
    float* out = (float*)d_out;

    cudaFuncSetAttribute(nv_main_kernel,
                         cudaFuncAttributeMaxDynamicSharedMemorySize,
                         SMEM_TOT);

    nv_zero_kernel<<<(N_ * K_ * C_ + 255) / 256, 256>>>();
    nv_main_kernel<<<N_ * SGROUPS, NTH, SMEM_TOT>>>(x, fc_w, fc_b);
    nv_finalize_kernel<<<N_, 128>>>(centroids, out);
}

// round 5
// speedup vs baseline: 2.2318x; 1.1068x over previous
#include <cuda_runtime.h>
#include <cuda_bf16.h>
#include <math.h>
#include <stdint.h>

#define N_  16
#define C_  128
#define S_  16384
#define K_  64
#define TS  128
#define TILES 4
#define SGROUPS (S_ / (TS * TILES))   // 32
#define NTH 256
#define LDX 136   // bf16 row stride for x tiles [s][c] (col 128 = ones)
#define LDW 136   // bf16 row stride for w [k][c]
#define LDT 136   // bf16 row stride for softT [k][s]

__device__ float g_vacc[N_ * K_ * C_];   // [n][k][c]
__device__ float g_asum[N_ * K_];        // [n][k]

// ---------------------------------------------------------------------------
__device__ __forceinline__ uint32_t s2u(const void* p) {
    uint32_t a;
    asm("{ .reg .u64 t; cvta.to.shared.u64 t, %1; cvt.u32.u64 %0, t; }"
        : "=r"(a) : "l"(p));
    return a;
}
__device__ __forceinline__ void ldsm4(uint32_t* r, uint32_t addr) {
    asm volatile("ldmatrix.sync.aligned.m8n8.x4.shared.b16 {%0,%1,%2,%3}, [%4];"
                 : "=r"(r[0]), "=r"(r[1]), "=r"(r[2]), "=r"(r[3]) : "r"(addr));
}
__device__ __forceinline__ void ldsm2t(uint32_t& r0, uint32_t& r1, uint32_t addr) {
    asm volatile("ldmatrix.sync.aligned.m8n8.x2.trans.shared.b16 {%0,%1}, [%2];"
                 : "=r"(r0), "=r"(r1) : "r"(addr));
}
__device__ __forceinline__ void mma_bf16(float* d, const uint32_t* a,
                                         uint32_t b0, uint32_t b1) {
    asm volatile("mma.sync.aligned.m16n8k16.row.col.f32.bf16.bf16.f32 "
                 "{%0,%1,%2,%3}, {%4,%5,%6,%7}, {%8,%9}, {%0,%1,%2,%3};"
                 : "+f"(d[0]), "+f"(d[1]), "+f"(d[2]), "+f"(d[3])
                 : "r"(a[0]), "r"(a[1]), "r"(a[2]), "r"(a[3]), "r"(b0), "r"(b1));
}

// ---------------------------------------------------------------------------
__global__ void nv_zero_kernel() {
    int i = blockIdx.x * blockDim.x + threadIdx.x;
    if (i < N_ * K_ * C_) g_vacc[i] = 0.0f;
    if (i < N_ * K_)      g_asum[i] = 0.0f;
}

// ---------------------------------------------------------------------------
// smem byte offsets
#define OFF_XH   0
#define OFF_XL   34816
#define OFF_WH   69632
#define OFF_WL   87040
#define OFF_SH   104448
#define OFF_SL   121856
#define OFF_BB   139264
#define OFF_PN   139520
#define SMEM_TOT 140544

__global__ __launch_bounds__(NTH, 1)
void nv_main_kernel(const float* __restrict__ x,
                    const float* __restrict__ fc_w,
                    const float* __restrict__ fc_b) {
    extern __shared__ char smem[];
    __nv_bfloat16* XH  = (__nv_bfloat16*)(smem + OFF_XH);
    __nv_bfloat16* XL  = (__nv_bfloat16*)(smem + OFF_XL);
    __nv_bfloat16* WH  = (__nv_bfloat16*)(smem + OFF_WH);
    __nv_bfloat16* WL  = (__nv_bfloat16*)(smem + OFF_WL);
    __nv_bfloat16* SHm = (__nv_bfloat16*)(smem + OFF_SH);
    __nv_bfloat16* SLm = (__nv_bfloat16*)(smem + OFF_SL);
    float* BB = (float*)(smem + OFF_BB);
    float* PN = (float*)(smem + OFF_PN);

    const uint32_t XHu = s2u(XH), XLu = s2u(XL), WHu = s2u(WH), WLu = s2u(WL);
    const uint32_t SHu = s2u(SHm), SLu = s2u(SLm);

    const int n   = blockIdx.x >> 5;
    const int g   = blockIdx.x & (SGROUPS - 1);
    const int tid = threadIdx.x;
    const int l   = tid & 31;
    const int w   = tid >> 5;
    const int sl  = tid & 127;     // position in tile (norm/convert)
    const int hh  = tid >> 7;      // channel half

    // ---- load fc_w hi/lo + bias (once per block) ----
    for (int i = tid; i < K_ * C_; i += NTH) {
        int k = i >> 7, c = i & 127;
        float v = fc_w[i];
        __nv_bfloat16 hi = __float2bfloat16(v);
        WH[k * LDW + c] = hi;
        WL[k * LDW + c] = __float2bfloat16(v - __bfloat162float(hi));
    }
    if (tid < K_) BB[tid] = fc_b[tid];
    __syncthreads();

    // per-thread bias registers for its 16 logit columns
    const int cst = (l & 3) * 2;
    float bias_r[8][2];
    #pragma unroll
    for (int j = 0; j < 8; j++) {
        bias_r[j][0] = BB[j * 8 + cst];
        bias_r[j][1] = BB[j * 8 + cst + 1];
    }

    // persistent GEMM2 accumulators: warp w owns m16 stripe (w&3), n64 (w>>2)
    const int m0b = (w & 3) * 16;
    const int nb  = (w >> 2) * 64;
    float vacc[8][4];
    #pragma unroll
    for (int j = 0; j < 8; j++)
        #pragma unroll
        for (int q = 0; q < 4; q++) vacc[j][q] = 0.0f;
    float vacc8[4] = {0.f, 0.f, 0.f, 0.f};   // ones-column (a_sum), nb==64 warps

    #pragma unroll 1
    for (int t = 0; t < TILES; t++) {
        const int s0 = g * (TS * TILES) + t * TS;
        const float* xg = x + (size_t)n * C_ * S_ + s0;
        __syncthreads();                         // A: prev tile consumers done

        // ---- pass 1: squared-sum halves ----
        float ss = 0.0f;
        #pragma unroll 8
        for (int c = hh * 64; c < hh * 64 + 64; c++) {
            float v = xg[(size_t)c * S_ + sl];
            ss = fmaf(v, v, ss);
        }
        PN[sl * 2 + hh] = ss;
        __syncthreads();                         // S1

        // ---- pass 2: normalize + bf16 hi/lo convert ----
        float scale = 1.0f / fmaxf(sqrtf(PN[sl * 2] + PN[sl * 2 + 1]), 1e-12f);
        #pragma unroll 4
        for (int c = hh * 64; c < hh * 64 + 64; c += 2) {
            float v0 = xg[(size_t)c * S_ + sl] * scale;
            float v1 = xg[(size_t)(c + 1) * S_ + sl] * scale;
            __nv_bfloat16 h0 = __float2bfloat16(v0);
            __nv_bfloat16 h1 = __float2bfloat16(v1);
            __nv_bfloat162 hp; hp.x = h0; hp.y = h1;
            __nv_bfloat162 lp;
            lp.x = __float2bfloat16(v0 - __bfloat162float(h0));
            lp.y = __float2bfloat16(v1 - __bfloat162float(h1));
            *(__nv_bfloat162*)&XH[sl * LDX + c] = hp;
            *(__nv_bfloat162*)&XL[sl * LDX + c] = lp;
        }
        if (hh == 0) XH[sl * LDX + 128] = __float2bfloat16(1.0f);  // ones col
        __syncthreads();                         // S2: XH/XL ready

        // ---- GEMM1: logits[TS,K] = xn @ w^T  (3-term bf16 hi/lo) ----
        float lacc[8][4];
        #pragma unroll
        for (int j = 0; j < 8; j++)
            #pragma unroll
            for (int q = 0; q < 4; q++) lacc[j][q] = 0.0f;
        {
            const int m0 = w * 16;
            uint32_t aoffA = (uint32_t)(((m0 + (l & 15)) * LDX + ((l >> 4) << 3)) * 2);
            uint32_t boffB = (uint32_t)(((((l >> 4) << 3) + (l & 7)) * LDW
                                        + (((l >> 3) & 1) << 3)) * 2);
            #pragma unroll 1
            for (int kc = 0; kc < 8; kc++) {
                uint32_t axh[4], axl[4];
                ldsm4(axh, XHu + aoffA + kc * 32);
                ldsm4(axl, XLu + aoffA + kc * 32);
                #pragma unroll
                for (int j = 0; j < 4; j++) {
                    uint32_t bwh[4], bwl[4];
                    uint32_t bo = boffB + kc * 32 + j * 16 * LDW * 2;
                    ldsm4(bwh, WHu + bo);
                    ldsm4(bwl, WLu + bo);
                    mma_bf16(lacc[2*j],   axh, bwh[0], bwh[1]);
                    mma_bf16(lacc[2*j+1], axh, bwh[2], bwh[3]);
                    mma_bf16(lacc[2*j],   axl, bwh[0], bwh[1]);
                    mma_bf16(lacc[2*j+1], axl, bwh[2], bwh[3]);
                    mma_bf16(lacc[2*j],   axh, bwl[0], bwl[1]);
                    mma_bf16(lacc[2*j+1], axh, bwl[2], bwl[3]);
                }
            }
        }

        // ---- register softmax over k (4-lane groups share a row) ----
        {
            const int m0 = w * 16;
            const int r0 = m0 + (l >> 2);           // row (s) for acc[0..1]
            float mx0 = -INFINITY, mx1 = -INFINITY;
            #pragma unroll
            for (int j = 0; j < 8; j++) {
                lacc[j][0] += bias_r[j][0]; lacc[j][1] += bias_r[j][1];
                lacc[j][2] += bias_r[j][0]; lacc[j][3] += bias_r[j][1];
                mx0 = fmaxf(mx0, fmaxf(lacc[j][0], lacc[j][1]));
                mx1 = fmaxf(mx1, fmaxf(lacc[j][2], lacc[j][3]));
            }
            mx0 = fmaxf(mx0, __shfl_xor_sync(0xffffffffu, mx0, 1));
            mx0 = fmaxf(mx0, __shfl_xor_sync(0xffffffffu, mx0, 2));
            mx1 = fmaxf(mx1, __shfl_xor_sync(0xffffffffu, mx1, 1));
            mx1 = fmaxf(mx1, __shfl_xor_sync(0xffffffffu, mx1, 2));
            float se0 = 0.0f, se1 = 0.0f;
            #pragma unroll
            for (int j = 0; j < 8; j++) {
                float e;
                e = __expf(lacc[j][0] - mx0); lacc[j][0] = e; se0 += e;
                e = __expf(lacc[j][1] - mx0); lacc[j][1] = e; se0 += e;
                e = __expf(lacc[j][2] - mx1); lacc[j][2] = e; se1 += e;
                e = __expf(lacc[j][3] - mx1); lacc[j][3] = e; se1 += e;
            }
            se0 += __shfl_xor_sync(0xffffffffu, se0, 1);
            se0 += __shfl_xor_sync(0xffffffffu, se0, 2);
            se1 += __shfl_xor_sync(0xffffffffu, se1, 1);
            se1 += __shfl_xor_sync(0xffffffffu, se1, 2);
            float inv0 = 1.0f / se0, inv1 = 1.0f / se1;

            #pragma unroll
            for (int j = 0; j < 8; j++) {
                int k0 = j * 8 + cst;
                float v00 = lacc[j][0] * inv0, v01 = lacc[j][1] * inv0;
                float v10 = lacc[j][2] * inv1, v11 = lacc[j][3] * inv1;
                __nv_bfloat16 h;
                h = __float2bfloat16(v00);
                SHm[k0 * LDT + r0] = h;
                SLm[k0 * LDT + r0] = __float2bfloat16(v00 - __bfloat162float(h));
                h = __float2bfloat16(v01);
                SHm[(k0 + 1) * LDT + r0] = h;
                SLm[(k0 + 1) * LDT + r0] = __float2bfloat16(v01 - __bfloat162float(h));
                h = __float2bfloat16(v10);
                SHm[k0 * LDT + r0 + 8] = h;
                SLm[k0 * LDT + r0 + 8] = __float2bfloat16(v10 - __bfloat162float(h));
                h = __float2bfloat16(v11);
                SHm[(k0 + 1) * LDT + r0 + 8] = h;
                SLm[(k0 + 1) * LDT + r0 + 8] = __float2bfloat16(v11 - __bfloat162float(h));
            }
        }
        __syncthreads();                         // S3: soft ready

        // ---- GEMM2: vlad[K,C] += softT @ xn (3-term) + ones-col a_sum ----
        #pragma unroll 1
        for (int ks = 0; ks < 8; ks++) {
            int sb = ks * 16;
            uint32_t aoff = (uint32_t)(((m0b + (l & 15)) * LDT + sb
                                       + ((l >> 4) << 3)) * 2);
            uint32_t ash[4], asl[4];
            ldsm4(ash, SHu + aoff);
            ldsm4(asl, SLu + aoff);
            uint32_t boff = (uint32_t)(((sb + (l & 15)) * LDX) * 2);
            #pragma unroll
            for (int j = 0; j < 8; j++) {
                int n0 = nb + j * 8;
                uint32_t bxh0, bxh1, bxl0, bxl1;
                ldsm2t(bxh0, bxh1, XHu + boff + n0 * 2);
                ldsm2t(bxl0, bxl1, XLu + boff + n0 * 2);
                mma_bf16(vacc[j], ash, bxh0, bxh1);
                mma_bf16(vacc[j], asl, bxh0, bxh1);
                mma_bf16(vacc[j], ash, bxl0, bxl1);
            }
            if (nb == 64) {   // ones column at c=128 -> a_sum
                uint32_t bxh0, bxh1;
                ldsm2t(bxh0, bxh1, XHu + boff + 128 * 2);
                mma_bf16(vacc8, ash, bxh0, bxh1);
                mma_bf16(vacc8, asl, bxh0, bxh1);
            }
        }
    }

    // ---- atomic volley ----
    float* vdst = g_vacc + n * K_ * C_;
    {
        int r0 = m0b + (l >> 2);
        #pragma unroll
        for (int j = 0; j < 8; j++) {
            int c = nb + j * 8 + cst;
            atomicAdd(&vdst[r0 * C_ + c],           vacc[j][0]);
            atomicAdd(&vdst[r0 * C_ + c + 1],       vacc[j][1]);
            atomicAdd(&vdst[(r0 + 8) * C_ + c],     vacc[j][2]);
            atomicAdd(&vdst[(r0 + 8) * C_ + c + 1], vacc[j][3]);
        }
        if (nb == 64 && (l & 3) == 0) {
            atomicAdd(&g_asum[n * K_ + r0],     vacc8[0]);
            atomicAdd(&g_asum[n * K_ + r0 + 8], vacc8[2]);
        }
    }
}

// ---------------------------------------------------------------------------
__global__ __launch_bounds__(128)
void nv_finalize_kernel(const float* __restrict__ centroids,
                        float* __restrict__ out) {
    __shared__ float vsh[K_ * C_];
    __shared__ float wsum[4];

    const int n   = blockIdx.x;
    const int tid = threadIdx.x;
    const int k   = tid >> 1;
    const int cb  = (tid & 1) * 64;

    const float* acc = g_vacc + n * K_ * C_;
    const float  ak  = g_asum[n * K_ + k];

    float ssk = 0.0f;
    #pragma unroll 8
    for (int c = 0; c < 64; c++) {
        int idx = k * C_ + cb + c;
        float v = acc[idx] - ak * centroids[idx];
        vsh[idx] = v;
        ssk = fmaf(v, v, ssk);
    }
    ssk += __shfl_xor_sync(0xffffffff, ssk, 1);
    float rinv = 1.0f / fmaxf(sqrtf(ssk), 1e-12f);

    float tot = 0.0f;
    #pragma unroll 8
    for (int c = 0; c < 64; c++) {
        int idx = k * C_ + cb + c;
        float tv = vsh[idx] * rinv;
        vsh[idx] = tv;
        tot = fmaf(tv, tv, tot);
    }
    #pragma unroll
    for (int off = 16; off > 0; off >>= 1)
        tot += __shfl_xor_sync(0xffffffff, tot, off);
    if ((tid & 31) == 0) wsum[tid >> 5] = tot;
    __syncthreads();
    float total = wsum[0] + wsum[1] + wsum[2] + wsum[3];
    float ginv = 1.0f / fmaxf(sqrtf(total), 1e-12f);

    float* od = out + (size_t)n * K_ * C_;
    for (int i = tid; i < K_ * C_; i += 128)
        od[i] = vsh[i] * ginv;
}

// ---------------------------------------------------------------------------
extern "C" void kernel_launch(void* const* d_in, const int* in_sizes, int n_in,
                              void* d_out, int out_size) {
    const float* x         = (const float*)d_in[0];
    const float* fc_w      = (const float*)d_in[1];
    const float* fc_b      = (const float*)d_in[2];
    const float* centroids = (const float*)d_in[3];
    float* out = (float*)d_out;

    cudaFuncSetAttribute(nv_main_kernel,
                         cudaFuncAttributeMaxDynamicSharedMemorySize,
                         SMEM_TOT);

    nv_zero_kernel<<<(N_ * K_ * C_ + 255) / 256, 256>>>();
    nv_main_kernel<<<N_ * SGROUPS, NTH, SMEM_TOT>>>(x, fc_w, fc_b);
    nv_finalize_kernel<<<N_, 128>>>(centroids, out);
}